// round 4
// baseline (speedup 1.0000x reference)
#include <cuda_runtime.h>
#include <cuda_bf16.h>

#define BB   8
#define NPT  2048
#define KNN  16
#define H    128
#define LL   4
#define CDIM 128
#define EPS  1e-12f
#define P    8

// ---------------- scratch (static device globals; no runtime alloc) --------
__device__ float g_bufA[BB * NPT * 3 * H];   // point-major [pt][d][h]
__device__ float g_bufB[BB * NPT * 3 * H];
__device__ int   g_idx [BB * NPT * KNN];
__device__ float g_g  [BB * 3 * H];          // [b][d][h]
__device__ float g_gp [BB * 3 * H];          // Gs_global @ g, [b][d][h]

// ---------------- kNN: per-batch brute force, top-16 by insertion ----------
__global__ void knn_kernel(const float* __restrict__ x) {
    int b = blockIdx.y;
    int i = blockIdx.x * blockDim.x + threadIdx.x;
    __shared__ float px[NPT], py[NPT], pz[NPT], sq[NPT];
    const float* xb = x + b * 3 * NPT;
    for (int n = threadIdx.x; n < NPT; n += blockDim.x) {
        float a = xb[n], c = xb[NPT + n], e = xb[2 * NPT + n];
        px[n] = a; py[n] = c; pz[n] = e;
        sq[n] = a * a + c * c + e * e;
    }
    __syncthreads();
    float qx = px[i], qy = py[i], qz = pz[i], qs = sq[i];
    float bd[KNN]; int bi[KNN];
#pragma unroll
    for (int t = 0; t < KNN; ++t) { bd[t] = 3.4e38f; bi[t] = 0; }
    for (int j = 0; j < NPT; ++j) {
        float dot = qx * px[j] + qy * py[j] + qz * pz[j];
        float d2  = qs + sq[j] - 2.0f * dot;
        if (d2 < bd[KNN - 1]) {
            int pos = KNN - 1;
            while (pos > 0 && d2 < bd[pos - 1]) {
                bd[pos] = bd[pos - 1]; bi[pos] = bi[pos - 1]; --pos;
            }
            bd[pos] = d2; bi[pos] = j;
        }
    }
    int base = (b * NPT + i) * KNN;
#pragma unroll
    for (int t = 0; t < KNN; ++t) g_idx[base + t] = bi[t];
}

// ---------------- input stage: y -> vec_lna(W_in, Wd_in) -> mean over K ----
__global__ __launch_bounds__(128, 1)
void input_kernel(const float* __restrict__ x,
                  const float* __restrict__ Win,
                  const float* __restrict__ Wdin) {
    int pt = blockIdx.x;
    int b  = pt >> 11;
    int n  = pt & (NPT - 1);
    int h  = threadIdx.x;
    int lane = h & 31, warp = h >> 5;

    __shared__ float ysh[3][3][KNN];     // [channel][dim][k]
    __shared__ float vsh[KNN][3][H];     // normalized features
    __shared__ float red[4][KNN];

    const float* xb = x + b * 3 * NPT;
    if (h < KNN) {
        float cx = xb[n], cy = xb[NPT + n], cz = xb[2 * NPT + n];
        int j = g_idx[pt * KNN + h];
        float nx = xb[j], ny = xb[NPT + j], nz = xb[2 * NPT + j];
        float nn  = sqrtf(cx * cx + cy * cy + cz * cz);
        float inv = 1.0f / fmaxf(nn, EPS);
        float dx = cx * inv, dy = cy * inv, dz = cz * inv;
        ysh[0][0][h] = dy * nz - dz * ny;
        ysh[0][1][h] = dz * nx - dx * nz;
        ysh[0][2][h] = dx * ny - dy * nx;
        ysh[1][0][h] = nx - cx; ysh[1][1][h] = ny - cy; ysh[1][2][h] = nz - cz;
        ysh[2][0][h] = cx;      ysh[2][1][h] = cy;      ysh[2][2][h] = cz;
    }
    __syncthreads();

    float w0 = Win[h * 3 + 0], w1 = Win[h * 3 + 1], w2 = Win[h * 3 + 2];
    float u[KNN][3];
    float nsq[KNN];
#pragma unroll
    for (int k = 0; k < KNN; ++k) {
        float s = 0.0f;
#pragma unroll
        for (int d = 0; d < 3; ++d) {
            float t = w0 * ysh[0][d][k] + w1 * ysh[1][d][k] + w2 * ysh[2][d][k];
            u[k][d] = t; s += t * t;
        }
        nsq[k] = s;
    }
    // channel-norm reduction across all 128 threads per k
#pragma unroll
    for (int k = 0; k < KNN; ++k) {
        float v = nsq[k];
        for (int o = 16; o > 0; o >>= 1) v += __shfl_xor_sync(0xffffffffu, v, o);
        if (lane == 0) red[warp][k] = v;
    }
    __syncthreads();
#pragma unroll
    for (int k = 0; k < KNN; ++k) {
        float cn  = sqrtf(red[0][k] + red[1][k] + red[2][k] + red[3][k]);
        float nrm = sqrtf(nsq[k]);
        float f   = (nrm / fmaxf(nrm, EPS)) / fmaxf(cn, EPS);
#pragma unroll
        for (int d = 0; d < 3; ++d) vsh[k][d][h] = u[k][d] * f;
    }
    __syncthreads();

    // kvec = Wd_in @ v  (the 12.9 GMAC stage)
    float kv[KNN][3];
#pragma unroll
    for (int k = 0; k < KNN; ++k)
#pragma unroll
        for (int d = 0; d < 3; ++d) kv[k][d] = 0.0f;

    const float4* wd4 = (const float4*)(Wdin + h * H);
#pragma unroll 1
    for (int c4 = 0; c4 < H / 4; ++c4) {
        float4 w4 = wd4[c4];
#pragma unroll
        for (int k = 0; k < KNN; ++k)
#pragma unroll
            for (int d = 0; d < 3; ++d) {
                float4 v4 = *(const float4*)&vsh[k][d][c4 * 4];
                kv[k][d] += w4.x * v4.x + w4.y * v4.y + w4.z * v4.z + w4.w * v4.w;
            }
    }

    // vec_act + mean over K
    float a0 = 0.0f, a1 = 0.0f, a2 = 0.0f;
#pragma unroll
    for (int k = 0; k < KNN; ++k) {
        float ka = kv[k][0], kb = kv[k][1], kc = kv[k][2];
        float kn  = sqrtf(ka * ka + kb * kb + kc * kc);
        float inv = 1.0f / fmaxf(kn, EPS);
        float k0 = ka * inv, k1 = kb * inv, k2 = kc * inv;
        float v0 = vsh[k][0][h], v1 = vsh[k][1][h], v2 = vsh[k][2][h];
        float dot = v0 * k0 + v1 * k1 + v2 * k2;
        float s = fminf(dot, 0.0f);
        a0 += v0 - s * k0; a1 += v1 - s * k1; a2 += v2 - s * k2;
    }
    float* o = g_bufA + pt * (3 * H);
    o[0 * H + h] = a0 * (1.0f / KNN);
    o[1 * H + h] = a1 * (1.0f / KNN);
    o[2 * H + h] = a2 * (1.0f / KNN);
}

// ---------------- per-point vec_lna: bufA -> bufB --------------------------
__global__ __launch_bounds__(128, 1)
void lna_kernel(const float* __restrict__ W, const float* __restrict__ Wd) {
    int g0 = blockIdx.x * P;
    int h  = threadIdx.x;
    int lane = h & 31, warp = h >> 5;
    __shared__ float ish[P][3][H];
    __shared__ float vsh[P][3][H];
    __shared__ float red[4][P];

    const float* src = g_bufA + g0 * 3 * H;
#pragma unroll
    for (int t = 0; t < P * 3; ++t) ((float*)ish)[t * H + h] = src[t * H + h];
    __syncthreads();

    float u[P][3];
#pragma unroll
    for (int p = 0; p < P; ++p)
#pragma unroll
        for (int d = 0; d < 3; ++d) u[p][d] = 0.0f;

    const float4* wr4 = (const float4*)(W + h * H);
#pragma unroll 2
    for (int c4 = 0; c4 < H / 4; ++c4) {
        float4 w4 = wr4[c4];
#pragma unroll
        for (int p = 0; p < P; ++p)
#pragma unroll
            for (int d = 0; d < 3; ++d) {
                float4 v4 = *(const float4*)&ish[p][d][c4 * 4];
                u[p][d] += w4.x * v4.x + w4.y * v4.y + w4.z * v4.z + w4.w * v4.w;
            }
    }

    float nsq[P];
#pragma unroll
    for (int p = 0; p < P; ++p) {
        float s = u[p][0]*u[p][0] + u[p][1]*u[p][1] + u[p][2]*u[p][2];
        nsq[p] = s;
        float v = s;
        for (int o = 16; o > 0; o >>= 1) v += __shfl_xor_sync(0xffffffffu, v, o);
        if (lane == 0) red[warp][p] = v;
    }
    __syncthreads();
#pragma unroll
    for (int p = 0; p < P; ++p) {
        float cn  = sqrtf(red[0][p] + red[1][p] + red[2][p] + red[3][p]);
        float nrm = sqrtf(nsq[p]);
        float f   = (nrm / fmaxf(nrm, EPS)) / fmaxf(cn, EPS);
#pragma unroll
        for (int d = 0; d < 3; ++d) { u[p][d] *= f; vsh[p][d][h] = u[p][d]; }
    }
    __syncthreads();

    float kv[P][3];
#pragma unroll
    for (int p = 0; p < P; ++p)
#pragma unroll
        for (int d = 0; d < 3; ++d) kv[p][d] = 0.0f;
    const float4* wd4 = (const float4*)(Wd + h * H);
#pragma unroll 2
    for (int c4 = 0; c4 < H / 4; ++c4) {
        float4 w4 = wd4[c4];
#pragma unroll
        for (int p = 0; p < P; ++p)
#pragma unroll
            for (int d = 0; d < 3; ++d) {
                float4 v4 = *(const float4*)&vsh[p][d][c4 * 4];
                kv[p][d] += w4.x * v4.x + w4.y * v4.y + w4.z * v4.z + w4.w * v4.w;
            }
    }

    float* dst = g_bufB + g0 * 3 * H;
#pragma unroll
    for (int p = 0; p < P; ++p) {
        float ka = kv[p][0], kb = kv[p][1], kc = kv[p][2];
        float kn  = sqrtf(ka * ka + kb * kb + kc * kc);
        float inv = 1.0f / fmaxf(kn, EPS);
        float k0 = ka * inv, k1 = kb * inv, k2 = kc * inv;
        float dot = u[p][0] * k0 + u[p][1] * k1 + u[p][2] * k2;
        float s = fminf(dot, 0.0f);
        dst[(p * 3 + 0) * H + h] = u[p][0] - s * k0;
        dst[(p * 3 + 1) * H + h] = u[p][1] - s * k1;
        dst[(p * 3 + 2) * H + h] = u[p][2] - s * k2;
    }
}

// ---------------- global mean over N of bufB -> g_g ------------------------
__global__ void mean_kernel() {
    int fl = blockIdx.x;             // b*384 + c,  c = d*128 + h
    int b = fl / (3 * H), c = fl % (3 * H);
    float s = 0.0f;
    for (int n = threadIdx.x; n < NPT; n += blockDim.x)
        s += g_bufB[(b * NPT + n) * (3 * H) + c];
    __shared__ float rs[4];
    for (int o = 16; o > 0; o >>= 1) s += __shfl_xor_sync(0xffffffffu, s, o);
    if ((threadIdx.x & 31) == 0) rs[threadIdx.x >> 5] = s;
    __syncthreads();
    if (threadIdx.x == 0)
        g_g[fl] = (rs[0] + rs[1] + rs[2] + rs[3]) * (1.0f / NPT);
}

// ---------------- gpart = Gs[:, H:2H] @ g per batch ------------------------
__global__ void gpart_kernel(const float* __restrict__ Gi) {
    int b = blockIdx.x;
    int t = threadIdx.x;             // 384 threads: t = d*128 + h
    __shared__ float gs[3 * H];
    gs[t] = g_g[b * 3 * H + t];
    __syncthreads();
    int d = t >> 7, h = t & 127;
    const float4* w4p = (const float4*)(Gi + h * (2 * H) + H);
    const float4* g4p = (const float4*)&gs[d * H];
    float s = 0.0f;
#pragma unroll
    for (int c = 0; c < H / 4; ++c) {
        float4 w = w4p[c], v = g4p[c];
        s += w.x * v.x + w.y * v.y + w.z * v.z + w.w * v.w;
    }
    g_gp[b * 3 * H + t] = s;
}

// -------- G-layer: vec_lna([h,g], Gs, Gds) + W_out accumulation ------------
__global__ __launch_bounds__(128, 1)
void glayer_kernel(const float* __restrict__ Gl, const float* __restrict__ Gd,
                   const float* __restrict__ Wout, float* __restrict__ obig,
                   int layer) {
    int g0 = blockIdx.x * P;
    int b  = g0 >> 11;
    int h  = threadIdx.x;
    int lane = h & 31, warp = h >> 5;
    __shared__ float ish[P][3][H];   // input, later reused for h2
    __shared__ float vsh[P][3][H];
    __shared__ float red[4][P];

    const float* src = g_bufB + g0 * 3 * H;
#pragma unroll
    for (int t = 0; t < P * 3; ++t) ((float*)ish)[t * H + h] = src[t * H + h];
    __syncthreads();

    float u[P][3];
#pragma unroll
    for (int d = 0; d < 3; ++d) {
        float gv = g_gp[b * 3 * H + d * H + h];
#pragma unroll
        for (int p = 0; p < P; ++p) u[p][d] = gv;
    }
    const float4* gr4 = (const float4*)(Gl + h * (2 * H));  // local H cols
#pragma unroll 2
    for (int c4 = 0; c4 < H / 4; ++c4) {
        float4 w4 = gr4[c4];
#pragma unroll
        for (int p = 0; p < P; ++p)
#pragma unroll
            for (int d = 0; d < 3; ++d) {
                float4 v4 = *(const float4*)&ish[p][d][c4 * 4];
                u[p][d] += w4.x * v4.x + w4.y * v4.y + w4.z * v4.z + w4.w * v4.w;
            }
    }

    float nsq[P];
#pragma unroll
    for (int p = 0; p < P; ++p) {
        float s = u[p][0]*u[p][0] + u[p][1]*u[p][1] + u[p][2]*u[p][2];
        nsq[p] = s;
        float v = s;
        for (int o = 16; o > 0; o >>= 1) v += __shfl_xor_sync(0xffffffffu, v, o);
        if (lane == 0) red[warp][p] = v;
    }
    __syncthreads();
#pragma unroll
    for (int p = 0; p < P; ++p) {
        float cn  = sqrtf(red[0][p] + red[1][p] + red[2][p] + red[3][p]);
        float nrm = sqrtf(nsq[p]);
        float f   = (nrm / fmaxf(nrm, EPS)) / fmaxf(cn, EPS);
#pragma unroll
        for (int d = 0; d < 3; ++d) { u[p][d] *= f; vsh[p][d][h] = u[p][d]; }
    }
    __syncthreads();

    float kv[P][3];
#pragma unroll
    for (int p = 0; p < P; ++p)
#pragma unroll
        for (int d = 0; d < 3; ++d) kv[p][d] = 0.0f;
    const float4* wd4 = (const float4*)(Gd + h * H);
#pragma unroll 2
    for (int c4 = 0; c4 < H / 4; ++c4) {
        float4 w4 = wd4[c4];
#pragma unroll
        for (int p = 0; p < P; ++p)
#pragma unroll
            for (int d = 0; d < 3; ++d) {
                float4 v4 = *(const float4*)&vsh[p][d][c4 * 4];
                kv[p][d] += w4.x * v4.x + w4.y * v4.y + w4.z * v4.z + w4.w * v4.w;
            }
    }

    // vec_act -> h2; write to g_bufA (next layer input) and ish (for W_out)
    float* dst = g_bufA + g0 * 3 * H;
#pragma unroll
    for (int p = 0; p < P; ++p) {
        float ka = kv[p][0], kb = kv[p][1], kc = kv[p][2];
        float kn  = sqrtf(ka * ka + kb * kb + kc * kc);
        float inv = 1.0f / fmaxf(kn, EPS);
        float k0 = ka * inv, k1 = kb * inv, k2 = kc * inv;
        float dot = u[p][0] * k0 + u[p][1] * k1 + u[p][2] * k2;
        float s = fminf(dot, 0.0f);
        float r0 = u[p][0] - s * k0, r1 = u[p][1] - s * k1, r2 = u[p][2] - s * k2;
        dst[(p * 3 + 0) * H + h] = r0;
        dst[(p * 3 + 1) * H + h] = r1;
        dst[(p * 3 + 2) * H + h] = r2;
        ish[p][0][h] = r0; ish[p][1][h] = r1; ish[p][2][h] = r2;
    }
    __syncthreads();

    // W_out slice for this layer: thread h = output channel cd
    float o[P][3];
#pragma unroll
    for (int p = 0; p < P; ++p)
#pragma unroll
        for (int d = 0; d < 3; ++d) o[p][d] = 0.0f;
    const float4* wo4 = (const float4*)(Wout + h * (LL * H) + layer * H);
#pragma unroll 2
    for (int c4 = 0; c4 < H / 4; ++c4) {
        float4 w4 = wo4[c4];
#pragma unroll
        for (int p = 0; p < P; ++p)
#pragma unroll
            for (int d = 0; d < 3; ++d) {
                float4 v4 = *(const float4*)&ish[p][d][c4 * 4];
                o[p][d] += w4.x * v4.x + w4.y * v4.y + w4.z * v4.z + w4.w * v4.w;
            }
    }
    int n0 = g0 & (NPT - 1);
#pragma unroll
    for (int d = 0; d < 3; ++d) {
        float* dptr = obig + ((b * CDIM + h) * 3 + d) * NPT + n0;
        if (layer == 0) {
#pragma unroll
            for (int p = 0; p < P; ++p) dptr[p] = o[p][d];
        } else {
#pragma unroll
            for (int p = 0; p < P; ++p) dptr[p] += o[p][d];
        }
    }
}

// ---------------- final mean over N of the big output ----------------------
__global__ void outmean_kernel(const float* __restrict__ obig,
                               float* __restrict__ om) {
    int r = blockIdx.x;              // (b*CD + cd)*3 + d
    float s = 0.0f;
    for (int n = threadIdx.x; n < NPT; n += blockDim.x)
        s += obig[r * NPT + n];
    __shared__ float rs[8];
    for (int o = 16; o > 0; o >>= 1) s += __shfl_xor_sync(0xffffffffu, s, o);
    if ((threadIdx.x & 31) == 0) rs[threadIdx.x >> 5] = s;
    __syncthreads();
    if (threadIdx.x == 0) {
        float t = 0.0f;
#pragma unroll
        for (int w = 0; w < 8; ++w) t += rs[w];
        om[r] = t * (1.0f / NPT);
    }
}

// ---------------------------------------------------------------------------
extern "C" void kernel_launch(void* const* d_in, const int* in_sizes, int n_in,
                              void* d_out, int out_size) {
    const float* x    = (const float*)d_in[0];
    const float* Win  = (const float*)d_in[1];
    const float* Wdin = (const float*)d_in[2];
    const float* Ws   = (const float*)d_in[3];
    const float* Wds  = (const float*)d_in[4];
    const float* Gs   = (const float*)d_in[5];
    const float* Gds  = (const float*)d_in[6];
    const float* Wout = (const float*)d_in[7];
    (void)in_sizes; (void)n_in; (void)out_size;

    float* out  = (float*)d_out;
    float* om   = out;                    // (B, CD, 3) mean
    float* obig = out + BB * CDIM * 3;    // (B, CD, 3, N)

    knn_kernel<<<dim3(NPT / 256, BB), 256>>>(x);
    input_kernel<<<BB * NPT, 128>>>(x, Win, Wdin);

    for (int i = 0; i < LL; ++i) {
        lna_kernel<<<BB * NPT / P, 128>>>(Ws + i * H * H, Wds + i * H * H);
        mean_kernel<<<BB * 3 * H, 128>>>();
        gpart_kernel<<<BB, 3 * H>>>(Gs + i * H * 2 * H);
        glayer_kernel<<<BB * NPT / P, 128>>>(Gs + i * H * 2 * H,
                                             Gds + i * H * H,
                                             Wout, obig, i);
    }
    outmean_kernel<<<BB * CDIM * 3, 256>>>(obig, om);
}

// round 5
// speedup vs baseline: 1.0302x; 1.0302x over previous
#include <cuda_runtime.h>
#include <cuda_bf16.h>

#define BB   8
#define NPT  2048
#define KNN  16
#define H    128
#define LL   4
#define CDIM 128
#define EPS  1e-12f
#define P    8
#define NG   (BB * NPT / P)     // 2048 groups of 8 points
#define GSZ  (3 * H * P)        // 3072 floats per group, layout [d][c][p]

union F2 { float2 f; unsigned long long u; };

#define FMA2(acc, a, b)   asm("fma.rn.f32x2 %0, %1, %2, %0;" : "+l"(acc) : "l"(a), "l"(b))
#define MUL2(d, a, b)     asm("mul.rn.f32x2 %0, %1, %2;"     : "=l"(d)   : "l"(a), "l"(b))
#define ADD2(acc, a)      asm("add.rn.f32x2 %0, %1, %0;"     : "+l"(acc) : "l"(a))
#define PACKF2(d, lo, hi) asm("mov.b64 %0, {%1, %2};"        : "=l"(d)   : "f"(lo), "f"(hi))

// ---------------- scratch (static device globals; no runtime alloc) --------
__device__ __align__(16) float g_bufA[NG * GSZ];
__device__ __align__(16) float g_bufB[NG * GSZ];
__device__ int   g_idx[BB * NPT * KNN];
__device__ float g_g [BB * 3 * H];
__device__ float g_gp[BB * 3 * H];

// ---------------- helpers --------------------------------------------------
__device__ __forceinline__ void vact(float v0, float v1, float v2,
                                     float k0, float k1, float k2,
                                     float& r0, float& r1, float& r2) {
    float kn  = sqrtf(k0 * k0 + k1 * k1 + k2 * k2);
    float inv = 1.0f / fmaxf(kn, EPS);
    float a = k0 * inv, b = k1 * inv, c = k2 * inv;
    float dot = v0 * a + v1 * b + v2 * c;
    float s = fminf(dot, 0.0f);
    r0 = v0 - s * a; r1 = v1 - s * b; r2 = v2 - s * c;
}

// matvec over H channels, 8 points (4 f32x2 pairs), 3 dims. v layout [d][c][P].
__device__ __forceinline__ void matvec8(const float* __restrict__ v,
                                        const float* __restrict__ wrow,
                                        F2 acc[3][4]) {
    const float4* w4p = (const float4*)wrow;
#pragma unroll 2
    for (int c4 = 0; c4 < 32; ++c4) {
        float4 w4 = w4p[c4];
        unsigned long long wp[4];
        PACKF2(wp[0], w4.x, w4.x);
        PACKF2(wp[1], w4.y, w4.y);
        PACKF2(wp[2], w4.z, w4.z);
        PACKF2(wp[3], w4.w, w4.w);
#pragma unroll
        for (int j = 0; j < 4; ++j) {
            int c = c4 * 4 + j;
#pragma unroll
            for (int d = 0; d < 3; ++d) {
                const ulonglong2* vp = (const ulonglong2*)(v + (d * H + c) * P);
                ulonglong2 va = vp[0];
                ulonglong2 vb = vp[1];
                FMA2(acc[d][0].u, wp[j], va.x);
                FMA2(acc[d][1].u, wp[j], va.y);
                FMA2(acc[d][2].u, wp[j], vb.x);
                FMA2(acc[d][3].u, wp[j], vb.y);
            }
        }
    }
}

// channel-equivariant normalize for 8 points held as pairs in acc
__device__ __forceinline__ void cnorm8(F2 acc[3][4],
                                       unsigned long long (*redu)[4],
                                       int lane, int warp) {
    F2 nsq[4];
#pragma unroll
    for (int q = 0; q < 4; ++q) {
        MUL2(nsq[q].u, acc[0][q].u, acc[0][q].u);
        FMA2(nsq[q].u, acc[1][q].u, acc[1][q].u);
        FMA2(nsq[q].u, acc[2][q].u, acc[2][q].u);
    }
#pragma unroll
    for (int q = 0; q < 4; ++q) {
        unsigned long long v = nsq[q].u;
#pragma unroll
        for (int o = 16; o > 0; o >>= 1) {
            unsigned long long s = __shfl_xor_sync(0xffffffffu, v, o);
            ADD2(v, s);
        }
        if (lane == 0) redu[warp][q] = v;
    }
    __syncthreads();
#pragma unroll
    for (int q = 0; q < 4; ++q) {
        F2 cs; cs.u = redu[0][q];
        ADD2(cs.u, redu[1][q]);
        ADD2(cs.u, redu[2][q]);
        ADD2(cs.u, redu[3][q]);
        float cnx = sqrtf(cs.f.x), cny = sqrtf(cs.f.y);
        float nx  = sqrtf(nsq[q].f.x), ny = sqrtf(nsq[q].f.y);
        float fx = (nx / fmaxf(nx, EPS)) / fmaxf(cnx, EPS);
        float fy = (ny / fmaxf(ny, EPS)) / fmaxf(cny, EPS);
        unsigned long long fp; PACKF2(fp, fx, fy);
#pragma unroll
        for (int d = 0; d < 3; ++d) MUL2(acc[d][q].u, acc[d][q].u, fp);
    }
}

// ---------------- kNN: per-batch brute force, top-16 by insertion ----------
__global__ void knn_kernel(const float* __restrict__ x) {
    int b = blockIdx.y;
    int i = blockIdx.x * blockDim.x + threadIdx.x;
    __shared__ float px[NPT], py[NPT], pz[NPT], sq[NPT];
    const float* xb = x + b * 3 * NPT;
    for (int n = threadIdx.x; n < NPT; n += blockDim.x) {
        float a = xb[n], c = xb[NPT + n], e = xb[2 * NPT + n];
        px[n] = a; py[n] = c; pz[n] = e;
        sq[n] = a * a + c * c + e * e;
    }
    __syncthreads();
    float qx = px[i], qy = py[i], qz = pz[i], qs = sq[i];
    float bd[KNN]; int bi[KNN];
#pragma unroll
    for (int t = 0; t < KNN; ++t) { bd[t] = 3.4e38f; bi[t] = 0; }
    for (int j = 0; j < NPT; ++j) {
        float dot = qx * px[j] + qy * py[j] + qz * pz[j];
        float d2  = qs + sq[j] - 2.0f * dot;
        if (d2 < bd[KNN - 1]) {
            int pos = KNN - 1;
            while (pos > 0 && d2 < bd[pos - 1]) {
                bd[pos] = bd[pos - 1]; bi[pos] = bi[pos - 1]; --pos;
            }
            bd[pos] = d2; bi[pos] = j;
        }
    }
    int base = (b * NPT + i) * KNN;
#pragma unroll
    for (int t = 0; t < KNN; ++t) g_idx[base + t] = bi[t];
}

// ---------------- input stage: y -> vec_lna(W_in, Wd_in) -> mean over K ----
// vsh layout: [d][c][k padded to 20]
__global__ __launch_bounds__(128)
void input_kernel(const float* __restrict__ x,
                  const float* __restrict__ Win,
                  const float* __restrict__ Wdin) {
    int pt = blockIdx.x;
    int b  = pt >> 11;
    int n  = pt & (NPT - 1);
    int h  = threadIdx.x;
    int lane = h & 31, warp = h >> 5;

    __shared__ __align__(16) float vsh[3 * H * 20];
    __shared__ float ysh[3][3][KNN];
    __shared__ float red[4][KNN];

    const float* xb = x + b * 3 * NPT;
    if (h < KNN) {
        float cx = xb[n], cy = xb[NPT + n], cz = xb[2 * NPT + n];
        int j = g_idx[pt * KNN + h];
        float nx = xb[j], ny = xb[NPT + j], nz = xb[2 * NPT + j];
        float nn  = sqrtf(cx * cx + cy * cy + cz * cz);
        float inv = 1.0f / fmaxf(nn, EPS);
        float dx = cx * inv, dy = cy * inv, dz = cz * inv;
        ysh[0][0][h] = dy * nz - dz * ny;
        ysh[0][1][h] = dz * nx - dx * nz;
        ysh[0][2][h] = dx * ny - dy * nx;
        ysh[1][0][h] = nx - cx; ysh[1][1][h] = ny - cy; ysh[1][2][h] = nz - cz;
        ysh[2][0][h] = cx;      ysh[2][1][h] = cy;      ysh[2][2][h] = cz;
    }
    __syncthreads();

    float w0 = Win[h * 3 + 0], w1 = Win[h * 3 + 1], w2 = Win[h * 3 + 2];
    float u[KNN][3];
    float nsq[KNN];
#pragma unroll
    for (int k = 0; k < KNN; ++k) {
        float s = 0.0f;
#pragma unroll
        for (int d = 0; d < 3; ++d) {
            float t = w0 * ysh[0][d][k] + w1 * ysh[1][d][k] + w2 * ysh[2][d][k];
            u[k][d] = t; s += t * t;
        }
        nsq[k] = s;
    }
#pragma unroll
    for (int k = 0; k < KNN; ++k) {
        float v = nsq[k];
        for (int o = 16; o > 0; o >>= 1) v += __shfl_xor_sync(0xffffffffu, v, o);
        if (lane == 0) red[warp][k] = v;
    }
    __syncthreads();

    float f[KNN];
#pragma unroll
    for (int k = 0; k < KNN; ++k) {
        float cn = sqrtf(red[0][k] + red[1][k] + red[2][k] + red[3][k]);
        float nr = sqrtf(nsq[k]);
        f[k] = (nr / fmaxf(nr, EPS)) / fmaxf(cn, EPS);
    }
#pragma unroll
    for (int d = 0; d < 3; ++d) {
        float* vb = vsh + (d * H + h) * 20;
#pragma unroll
        for (int k4 = 0; k4 < 4; ++k4) {
            float4 t = make_float4(u[k4 * 4 + 0][d] * f[k4 * 4 + 0],
                                   u[k4 * 4 + 1][d] * f[k4 * 4 + 1],
                                   u[k4 * 4 + 2][d] * f[k4 * 4 + 2],
                                   u[k4 * 4 + 3][d] * f[k4 * 4 + 3]);
            *(float4*)(vb + k4 * 4) = t;
        }
    }
    __syncthreads();

    // kvec = Wd_in @ v with packed f32x2 over k-pairs
    F2 a[3][8];
#pragma unroll
    for (int d = 0; d < 3; ++d)
#pragma unroll
        for (int q = 0; q < 8; ++q) a[d][q].u = 0ull;

    const float4* wd4 = (const float4*)(Wdin + h * H);
#pragma unroll 2
    for (int c4 = 0; c4 < 32; ++c4) {
        float4 w4 = wd4[c4];
        unsigned long long wp[4];
        PACKF2(wp[0], w4.x, w4.x);
        PACKF2(wp[1], w4.y, w4.y);
        PACKF2(wp[2], w4.z, w4.z);
        PACKF2(wp[3], w4.w, w4.w);
#pragma unroll
        for (int j = 0; j < 4; ++j) {
            int c = c4 * 4 + j;
#pragma unroll
            for (int d = 0; d < 3; ++d) {
                const ulonglong2* vp = (const ulonglong2*)(vsh + (d * H + c) * 20);
                ulonglong2 v0 = vp[0], v1 = vp[1], v2 = vp[2], v3 = vp[3];
                FMA2(a[d][0].u, wp[j], v0.x); FMA2(a[d][1].u, wp[j], v0.y);
                FMA2(a[d][2].u, wp[j], v1.x); FMA2(a[d][3].u, wp[j], v1.y);
                FMA2(a[d][4].u, wp[j], v2.x); FMA2(a[d][5].u, wp[j], v2.y);
                FMA2(a[d][6].u, wp[j], v3.x); FMA2(a[d][7].u, wp[j], v3.y);
            }
        }
    }

    // vec_act + mean over K
    float a0 = 0.0f, a1 = 0.0f, a2 = 0.0f;
#pragma unroll
    for (int k4 = 0; k4 < 4; ++k4) {
        float4 v0 = *(const float4*)(vsh + (0 * H + h) * 20 + k4 * 4);
        float4 v1 = *(const float4*)(vsh + (1 * H + h) * 20 + k4 * 4);
        float4 v2 = *(const float4*)(vsh + (2 * H + h) * 20 + k4 * 4);
#pragma unroll
        for (int e = 0; e < 4; ++e) {
            int k = k4 * 4 + e;
            int q = k >> 1;
            float vx = (e == 0) ? v0.x : (e == 1) ? v0.y : (e == 2) ? v0.z : v0.w;
            float vy = (e == 0) ? v1.x : (e == 1) ? v1.y : (e == 2) ? v1.z : v1.w;
            float vz = (e == 0) ? v2.x : (e == 1) ? v2.y : (e == 2) ? v2.z : v2.w;
            float kx = (k & 1) ? a[0][q].f.y : a[0][q].f.x;
            float ky = (k & 1) ? a[1][q].f.y : a[1][q].f.x;
            float kz = (k & 1) ? a[2][q].f.y : a[2][q].f.x;
            float r0, r1, r2;
            vact(vx, vy, vz, kx, ky, kz, r0, r1, r2);
            a0 += r0; a1 += r1; a2 += r2;
        }
    }
    int grp = pt >> 3, p = pt & 7;
    float* ob = g_bufA + grp * GSZ + p;
    ob[(0 * H + h) * P] = a0 * (1.0f / KNN);
    ob[(1 * H + h) * P] = a1 * (1.0f / KNN);
    ob[(2 * H + h) * P] = a2 * (1.0f / KNN);
}

// ---------------- per-point vec_lna: bufA -> bufB --------------------------
__global__ __launch_bounds__(128)
void lna_kernel(const float* __restrict__ W, const float* __restrict__ Wd) {
    int grp = blockIdx.x;
    int h = threadIdx.x, lane = h & 31, warp = h >> 5;
    __shared__ __align__(16) float ish[GSZ];
    __shared__ __align__(16) float vsh[GSZ];
    __shared__ unsigned long long redu[4][4];

    const float4* s4 = (const float4*)(g_bufA + grp * GSZ);
    float4* i4 = (float4*)ish;
#pragma unroll
    for (int t = 0; t < 6; ++t) i4[t * 128 + h] = s4[t * 128 + h];
    __syncthreads();

    F2 acc[3][4];
#pragma unroll
    for (int d = 0; d < 3; ++d)
#pragma unroll
        for (int q = 0; q < 4; ++q) acc[d][q].u = 0ull;
    matvec8(ish, W + h * H, acc);
    cnorm8(acc, redu, lane, warp);

#pragma unroll
    for (int d = 0; d < 3; ++d) {
        ulonglong2* vp = (ulonglong2*)(vsh + (d * H + h) * P);
        vp[0] = make_ulonglong2(acc[d][0].u, acc[d][1].u);
        vp[1] = make_ulonglong2(acc[d][2].u, acc[d][3].u);
    }
    __syncthreads();

    F2 kv[3][4];
#pragma unroll
    for (int d = 0; d < 3; ++d)
#pragma unroll
        for (int q = 0; q < 4; ++q) kv[d][q].u = 0ull;
    matvec8(vsh, Wd + h * H, kv);

    F2 r[3][4];
#pragma unroll
    for (int q = 0; q < 4; ++q) {
        float r0x, r1x, r2x, r0y, r1y, r2y;
        vact(acc[0][q].f.x, acc[1][q].f.x, acc[2][q].f.x,
             kv[0][q].f.x,  kv[1][q].f.x,  kv[2][q].f.x, r0x, r1x, r2x);
        vact(acc[0][q].f.y, acc[1][q].f.y, acc[2][q].f.y,
             kv[0][q].f.y,  kv[1][q].f.y,  kv[2][q].f.y, r0y, r1y, r2y);
        r[0][q].f = make_float2(r0x, r0y);
        r[1][q].f = make_float2(r1x, r1y);
        r[2][q].f = make_float2(r2x, r2y);
    }
    float* dst = g_bufB + grp * GSZ;
#pragma unroll
    for (int d = 0; d < 3; ++d) {
        ulonglong2* dp = (ulonglong2*)(dst + (d * H + h) * P);
        dp[0] = make_ulonglong2(r[d][0].u, r[d][1].u);
        dp[1] = make_ulonglong2(r[d][2].u, r[d][3].u);
    }
}

// ---------------- global mean over N of bufB -> g_g ------------------------
__global__ void mean_kernel() {
    int fl = blockIdx.x;                 // b*384 + c, c = d*128 + h
    int b = fl / (3 * H), c = fl % (3 * H);
    const float* base = g_bufB + (size_t)b * (NPT / P) * GSZ + c * P;
    float s = 0.0f;
    for (int i = threadIdx.x; i < 2 * (NPT / P); i += 128) {
        int g = i >> 1, q = i & 1;
        float4 v = *(const float4*)(base + g * GSZ + q * 4);
        s += (v.x + v.y) + (v.z + v.w);
    }
    __shared__ float rs[4];
    for (int o = 16; o > 0; o >>= 1) s += __shfl_xor_sync(0xffffffffu, s, o);
    if ((threadIdx.x & 31) == 0) rs[threadIdx.x >> 5] = s;
    __syncthreads();
    if (threadIdx.x == 0)
        g_g[fl] = (rs[0] + rs[1] + rs[2] + rs[3]) * (1.0f / NPT);
}

// ---------------- gpart = Gs[:, H:2H] @ g per batch ------------------------
__global__ void gpart_kernel(const float* __restrict__ Gi) {
    int b = blockIdx.x;
    int t = threadIdx.x;                 // 384 threads: t = d*128 + h
    __shared__ float gs[3 * H];
    gs[t] = g_g[b * 3 * H + t];
    __syncthreads();
    int d = t >> 7, h = t & 127;
    const float4* w4p = (const float4*)(Gi + h * (2 * H) + H);
    const float4* g4p = (const float4*)&gs[d * H];
    float s = 0.0f;
#pragma unroll
    for (int c = 0; c < H / 4; ++c) {
        float4 w = w4p[c], v = g4p[c];
        s += w.x * v.x + w.y * v.y + w.z * v.z + w.w * v.w;
    }
    g_gp[b * 3 * H + t] = s;
}

// -------- G-layer: vec_lna([h,g], Gs, Gds) + W_out accumulation ------------
__global__ __launch_bounds__(128)
void glayer_kernel(const float* __restrict__ Gl, const float* __restrict__ Gd,
                   const float* __restrict__ Wout, float* __restrict__ obig,
                   int layer) {
    int grp = blockIdx.x;
    int b = grp >> 8;
    int h = threadIdx.x, lane = h & 31, warp = h >> 5;
    __shared__ __align__(16) float ish[GSZ];
    __shared__ __align__(16) float vsh[GSZ];
    __shared__ unsigned long long redu[4][4];

    const float4* s4 = (const float4*)(g_bufB + grp * GSZ);
    float4* i4 = (float4*)ish;
#pragma unroll
    for (int t = 0; t < 6; ++t) i4[t * 128 + h] = s4[t * 128 + h];
    __syncthreads();

    F2 acc[3][4];
#pragma unroll
    for (int d = 0; d < 3; ++d) {
        float gv = g_gp[b * 3 * H + d * H + h];
        unsigned long long gp; PACKF2(gp, gv, gv);
#pragma unroll
        for (int q = 0; q < 4; ++q) acc[d][q].u = gp;
    }
    matvec8(ish, Gl + h * (2 * H), acc);
    cnorm8(acc, redu, lane, warp);

#pragma unroll
    for (int d = 0; d < 3; ++d) {
        ulonglong2* vp = (ulonglong2*)(vsh + (d * H + h) * P);
        vp[0] = make_ulonglong2(acc[d][0].u, acc[d][1].u);
        vp[1] = make_ulonglong2(acc[d][2].u, acc[d][3].u);
    }
    __syncthreads();

    F2 kv[3][4];
#pragma unroll
    for (int d = 0; d < 3; ++d)
#pragma unroll
        for (int q = 0; q < 4; ++q) kv[d][q].u = 0ull;
    matvec8(vsh, Gd + h * H, kv);

    F2 r[3][4];
#pragma unroll
    for (int q = 0; q < 4; ++q) {
        float r0x, r1x, r2x, r0y, r1y, r2y;
        vact(acc[0][q].f.x, acc[1][q].f.x, acc[2][q].f.x,
             kv[0][q].f.x,  kv[1][q].f.x,  kv[2][q].f.x, r0x, r1x, r2x);
        vact(acc[0][q].f.y, acc[1][q].f.y, acc[2][q].f.y,
             kv[0][q].f.y,  kv[1][q].f.y,  kv[2][q].f.y, r0y, r1y, r2y);
        r[0][q].f = make_float2(r0x, r0y);
        r[1][q].f = make_float2(r1x, r1y);
        r[2][q].f = make_float2(r2x, r2y);
    }
    float* dst = g_bufA + grp * GSZ;
#pragma unroll
    for (int d = 0; d < 3; ++d) {
        ulonglong2 lo = make_ulonglong2(r[d][0].u, r[d][1].u);
        ulonglong2 hi = make_ulonglong2(r[d][2].u, r[d][3].u);
        ulonglong2* dp = (ulonglong2*)(dst + (d * H + h) * P);
        dp[0] = lo; dp[1] = hi;
        ulonglong2* ip = (ulonglong2*)(ish + (d * H + h) * P);
        ip[0] = lo; ip[1] = hi;
    }
    __syncthreads();

    // W_out slice for this layer (thread h = output channel cd)
    F2 o[3][4];
#pragma unroll
    for (int d = 0; d < 3; ++d)
#pragma unroll
        for (int q = 0; q < 4; ++q) o[d][q].u = 0ull;
    matvec8(ish, Wout + h * (LL * H) + layer * H, o);

    int n0 = (grp & 255) * P;
#pragma unroll
    for (int d = 0; d < 3; ++d) {
        ulonglong2* dp = (ulonglong2*)(obig + ((b * CDIM + h) * 3 + d) * NPT + n0);
        if (layer == 0) {
            dp[0] = make_ulonglong2(o[d][0].u, o[d][1].u);
            dp[1] = make_ulonglong2(o[d][2].u, o[d][3].u);
        } else {
            ulonglong2 e0 = dp[0], e1 = dp[1];
            ADD2(o[d][0].u, e0.x); ADD2(o[d][1].u, e0.y);
            ADD2(o[d][2].u, e1.x); ADD2(o[d][3].u, e1.y);
            dp[0] = make_ulonglong2(o[d][0].u, o[d][1].u);
            dp[1] = make_ulonglong2(o[d][2].u, o[d][3].u);
        }
    }
}

// ---------------- final mean over N of the big output ----------------------
__global__ void outmean_kernel(const float* __restrict__ obig,
                               float* __restrict__ om) {
    int r = blockIdx.x;                  // (b*CD + cd)*3 + d
    float s = 0.0f;
    for (int n = threadIdx.x; n < NPT; n += blockDim.x)
        s += obig[r * NPT + n];
    __shared__ float rs[8];
    for (int o = 16; o > 0; o >>= 1) s += __shfl_xor_sync(0xffffffffu, s, o);
    if ((threadIdx.x & 31) == 0) rs[threadIdx.x >> 5] = s;
    __syncthreads();
    if (threadIdx.x == 0) {
        float t = 0.0f;
#pragma unroll
        for (int w = 0; w < 8; ++w) t += rs[w];
        om[r] = t * (1.0f / NPT);
    }
}

// ---------------------------------------------------------------------------
extern "C" void kernel_launch(void* const* d_in, const int* in_sizes, int n_in,
                              void* d_out, int out_size) {
    const float* x    = (const float*)d_in[0];
    const float* Win  = (const float*)d_in[1];
    const float* Wdin = (const float*)d_in[2];
    const float* Ws   = (const float*)d_in[3];
    const float* Wds  = (const float*)d_in[4];
    const float* Gs   = (const float*)d_in[5];
    const float* Gds  = (const float*)d_in[6];
    const float* Wout = (const float*)d_in[7];
    (void)in_sizes; (void)n_in; (void)out_size;

    float* out  = (float*)d_out;
    float* om   = out;                    // (B, CD, 3) mean
    float* obig = out + BB * CDIM * 3;    // (B, CD, 3, N)

    knn_kernel<<<dim3(NPT / 256, BB), 256>>>(x);
    input_kernel<<<BB * NPT, 128>>>(x, Win, Wdin);

    for (int i = 0; i < LL; ++i) {
        lna_kernel<<<NG, 128>>>(Ws + i * H * H, Wds + i * H * H);
        mean_kernel<<<BB * 3 * H, 128>>>();
        gpart_kernel<<<BB, 3 * H>>>(Gs + i * H * 2 * H);
        glayer_kernel<<<NG, 128>>>(Gs + i * H * 2 * H,
                                   Gds + i * H * H,
                                   Wout, obig, i);
    }
    outmean_kernel<<<BB * CDIM * 3, 256>>>(obig, om);
}

// round 6
// speedup vs baseline: 1.9854x; 1.9271x over previous
#include <cuda_runtime.h>
#include <cuda_bf16.h>

#define BB   8
#define NPT  2048
#define KNN  16
#define H    128
#define LL   4
#define CDIM 128
#define EPS  1e-12f
#define P    8
#define NG   (BB * NPT / P)     // 2048 groups of 8 points
#define GSZ  (3 * H * P)        // 3072 floats per group, layout [d][c][p]

union F2 { float2 f; unsigned long long u; };

#define FMA2(acc, a, b)   asm("fma.rn.f32x2 %0, %1, %2, %0;" : "+l"(acc) : "l"(a), "l"(b))
#define MUL2(d, a, b)     asm("mul.rn.f32x2 %0, %1, %2;"     : "=l"(d)   : "l"(a), "l"(b))
#define ADD2(acc, a)      asm("add.rn.f32x2 %0, %1, %0;"     : "+l"(acc) : "l"(a))
#define PACKF2(d, lo, hi) asm("mov.b64 %0, {%1, %2};"        : "=l"(d)   : "f"(lo), "f"(hi))

// ---------------- scratch (static device globals; no runtime alloc) --------
__device__ __align__(16) float g_bufA[NG * GSZ];
__device__ __align__(16) float g_bufB[NG * GSZ];
__device__ int   g_idx[BB * NPT * KNN];
__device__ float g_g [BB * 3 * H];
__device__ float g_gp[BB * 3 * H];

// ---------------- helpers --------------------------------------------------
__device__ __forceinline__ void vact(float v0, float v1, float v2,
                                     float k0, float k1, float k2,
                                     float& r0, float& r1, float& r2) {
    float kn  = sqrtf(k0 * k0 + k1 * k1 + k2 * k2);
    float inv = 1.0f / fmaxf(kn, EPS);
    float a = k0 * inv, b = k1 * inv, c = k2 * inv;
    float dot = v0 * a + v1 * b + v2 * c;
    float s = fminf(dot, 0.0f);
    r0 = v0 - s * a; r1 = v1 - s * b; r2 = v2 - s * c;
}

// matvec over H channels, 8 points (4 f32x2 pairs), 3 dims. v layout [d][c][P].
__device__ __forceinline__ void matvec8(const float* __restrict__ v,
                                        const float* __restrict__ wrow,
                                        F2 acc[3][4]) {
    const float4* w4p = (const float4*)wrow;
#pragma unroll 2
    for (int c4 = 0; c4 < 32; ++c4) {
        float4 w4 = w4p[c4];
        unsigned long long wp[4];
        PACKF2(wp[0], w4.x, w4.x);
        PACKF2(wp[1], w4.y, w4.y);
        PACKF2(wp[2], w4.z, w4.z);
        PACKF2(wp[3], w4.w, w4.w);
#pragma unroll
        for (int j = 0; j < 4; ++j) {
            int c = c4 * 4 + j;
#pragma unroll
            for (int d = 0; d < 3; ++d) {
                const ulonglong2* vp = (const ulonglong2*)(v + (d * H + c) * P);
                ulonglong2 va = vp[0];
                ulonglong2 vb = vp[1];
                FMA2(acc[d][0].u, wp[j], va.x);
                FMA2(acc[d][1].u, wp[j], va.y);
                FMA2(acc[d][2].u, wp[j], vb.x);
                FMA2(acc[d][3].u, wp[j], vb.y);
            }
        }
    }
}

// channel-equivariant normalize for 8 points held as pairs in acc
__device__ __forceinline__ void cnorm8(F2 acc[3][4],
                                       unsigned long long (*redu)[4],
                                       int lane, int warp) {
    F2 nsq[4];
#pragma unroll
    for (int q = 0; q < 4; ++q) {
        MUL2(nsq[q].u, acc[0][q].u, acc[0][q].u);
        FMA2(nsq[q].u, acc[1][q].u, acc[1][q].u);
        FMA2(nsq[q].u, acc[2][q].u, acc[2][q].u);
    }
#pragma unroll
    for (int q = 0; q < 4; ++q) {
        unsigned long long v = nsq[q].u;
#pragma unroll
        for (int o = 16; o > 0; o >>= 1) {
            unsigned long long s = __shfl_xor_sync(0xffffffffu, v, o);
            ADD2(v, s);
        }
        if (lane == 0) redu[warp][q] = v;
    }
    __syncthreads();
#pragma unroll
    for (int q = 0; q < 4; ++q) {
        F2 cs; cs.u = redu[0][q];
        ADD2(cs.u, redu[1][q]);
        ADD2(cs.u, redu[2][q]);
        ADD2(cs.u, redu[3][q]);
        float cnx = sqrtf(cs.f.x), cny = sqrtf(cs.f.y);
        float nx  = sqrtf(nsq[q].f.x), ny = sqrtf(nsq[q].f.y);
        float fx = (nx / fmaxf(nx, EPS)) / fmaxf(cnx, EPS);
        float fy = (ny / fmaxf(ny, EPS)) / fmaxf(cny, EPS);
        unsigned long long fp; PACKF2(fp, fx, fy);
#pragma unroll
        for (int d = 0; d < 3; ++d) MUL2(acc[d][q].u, acc[d][q].u, fp);
    }
}

// ---------------- kNN: register-resident branch-free top-16 ----------------
// 128 blocks (16 x 8 batches), 128 threads. Top-16 kept fully in registers
// via a statically-indexed bubble insertion (no local memory, no dynamic idx).
__global__ __launch_bounds__(128)
void knn_kernel(const float* __restrict__ x) {
    int b = blockIdx.y;
    int i = blockIdx.x * blockDim.x + threadIdx.x;
    __shared__ float px[NPT], py[NPT], pz[NPT], sq[NPT];
    const float* xb = x + b * 3 * NPT;
    for (int n = threadIdx.x; n < NPT; n += blockDim.x) {
        float a = xb[n], c = xb[NPT + n], e = xb[2 * NPT + n];
        px[n] = a; py[n] = c; pz[n] = e;
        sq[n] = a * a + c * c + e * e;
    }
    __syncthreads();
    float qx = px[i], qy = py[i], qz = pz[i], qs = sq[i];
    float bd[KNN]; int bi[KNN];
#pragma unroll
    for (int t = 0; t < KNN; ++t) { bd[t] = 3.4e38f; bi[t] = 0; }

#pragma unroll 4
    for (int j = 0; j < NPT; ++j) {
        float dot = qx * px[j] + qy * py[j] + qz * pz[j];
        float d2  = fmaf(-2.0f, dot, qs + sq[j]);
        if (d2 < bd[KNN - 1]) {
            float cd = d2; int ci = j;
#pragma unroll
            for (int t = 0; t < KNN; ++t) {
                bool lt = cd < bd[t];
                float nd = lt ? cd    : bd[t];
                int   ni = lt ? ci    : bi[t];
                float od = lt ? bd[t] : cd;
                int   oi = lt ? bi[t] : ci;
                bd[t] = nd; bi[t] = ni;
                cd = od; ci = oi;
            }
        }
    }
    int base = (b * NPT + i) * KNN;
#pragma unroll
    for (int t = 0; t < KNN; ++t) g_idx[base + t] = bi[t];
}

// ---------------- input stage: y -> vec_lna(W_in, Wd_in) -> mean over K ----
// vsh layout: [d][c][k padded to 20]
__global__ __launch_bounds__(128)
void input_kernel(const float* __restrict__ x,
                  const float* __restrict__ Win,
                  const float* __restrict__ Wdin) {
    int pt = blockIdx.x;
    int b  = pt >> 11;
    int n  = pt & (NPT - 1);
    int h  = threadIdx.x;
    int lane = h & 31, warp = h >> 5;

    __shared__ __align__(16) float vsh[3 * H * 20];
    __shared__ float ysh[3][3][KNN];
    __shared__ float red[4][KNN];

    const float* xb = x + b * 3 * NPT;
    if (h < KNN) {
        float cx = xb[n], cy = xb[NPT + n], cz = xb[2 * NPT + n];
        int j = g_idx[pt * KNN + h];
        float nx = xb[j], ny = xb[NPT + j], nz = xb[2 * NPT + j];
        float nn  = sqrtf(cx * cx + cy * cy + cz * cz);
        float inv = 1.0f / fmaxf(nn, EPS);
        float dx = cx * inv, dy = cy * inv, dz = cz * inv;
        ysh[0][0][h] = dy * nz - dz * ny;
        ysh[0][1][h] = dz * nx - dx * nz;
        ysh[0][2][h] = dx * ny - dy * nx;
        ysh[1][0][h] = nx - cx; ysh[1][1][h] = ny - cy; ysh[1][2][h] = nz - cz;
        ysh[2][0][h] = cx;      ysh[2][1][h] = cy;      ysh[2][2][h] = cz;
    }
    __syncthreads();

    float w0 = Win[h * 3 + 0], w1 = Win[h * 3 + 1], w2 = Win[h * 3 + 2];
    float u[KNN][3];
    float nsq[KNN];
#pragma unroll
    for (int k = 0; k < KNN; ++k) {
        float s = 0.0f;
#pragma unroll
        for (int d = 0; d < 3; ++d) {
            float t = w0 * ysh[0][d][k] + w1 * ysh[1][d][k] + w2 * ysh[2][d][k];
            u[k][d] = t; s += t * t;
        }
        nsq[k] = s;
    }
#pragma unroll
    for (int k = 0; k < KNN; ++k) {
        float v = nsq[k];
        for (int o = 16; o > 0; o >>= 1) v += __shfl_xor_sync(0xffffffffu, v, o);
        if (lane == 0) red[warp][k] = v;
    }
    __syncthreads();

    float f[KNN];
#pragma unroll
    for (int k = 0; k < KNN; ++k) {
        float cn = sqrtf(red[0][k] + red[1][k] + red[2][k] + red[3][k]);
        float nr = sqrtf(nsq[k]);
        f[k] = (nr / fmaxf(nr, EPS)) / fmaxf(cn, EPS);
    }
#pragma unroll
    for (int d = 0; d < 3; ++d) {
        float* vb = vsh + (d * H + h) * 20;
#pragma unroll
        for (int k4 = 0; k4 < 4; ++k4) {
            float4 t = make_float4(u[k4 * 4 + 0][d] * f[k4 * 4 + 0],
                                   u[k4 * 4 + 1][d] * f[k4 * 4 + 1],
                                   u[k4 * 4 + 2][d] * f[k4 * 4 + 2],
                                   u[k4 * 4 + 3][d] * f[k4 * 4 + 3]);
            *(float4*)(vb + k4 * 4) = t;
        }
    }
    __syncthreads();

    // kvec = Wd_in @ v with packed f32x2 over k-pairs
    F2 a[3][8];
#pragma unroll
    for (int d = 0; d < 3; ++d)
#pragma unroll
        for (int q = 0; q < 8; ++q) a[d][q].u = 0ull;

    const float4* wd4 = (const float4*)(Wdin + h * H);
#pragma unroll 2
    for (int c4 = 0; c4 < 32; ++c4) {
        float4 w4 = wd4[c4];
        unsigned long long wp[4];
        PACKF2(wp[0], w4.x, w4.x);
        PACKF2(wp[1], w4.y, w4.y);
        PACKF2(wp[2], w4.z, w4.z);
        PACKF2(wp[3], w4.w, w4.w);
#pragma unroll
        for (int j = 0; j < 4; ++j) {
            int c = c4 * 4 + j;
#pragma unroll
            for (int d = 0; d < 3; ++d) {
                const ulonglong2* vp = (const ulonglong2*)(vsh + (d * H + c) * 20);
                ulonglong2 v0 = vp[0], v1 = vp[1], v2 = vp[2], v3 = vp[3];
                FMA2(a[d][0].u, wp[j], v0.x); FMA2(a[d][1].u, wp[j], v0.y);
                FMA2(a[d][2].u, wp[j], v1.x); FMA2(a[d][3].u, wp[j], v1.y);
                FMA2(a[d][4].u, wp[j], v2.x); FMA2(a[d][5].u, wp[j], v2.y);
                FMA2(a[d][6].u, wp[j], v3.x); FMA2(a[d][7].u, wp[j], v3.y);
            }
        }
    }

    // vec_act + mean over K
    float a0 = 0.0f, a1 = 0.0f, a2 = 0.0f;
#pragma unroll
    for (int k4 = 0; k4 < 4; ++k4) {
        float4 v0 = *(const float4*)(vsh + (0 * H + h) * 20 + k4 * 4);
        float4 v1 = *(const float4*)(vsh + (1 * H + h) * 20 + k4 * 4);
        float4 v2 = *(const float4*)(vsh + (2 * H + h) * 20 + k4 * 4);
#pragma unroll
        for (int e = 0; e < 4; ++e) {
            int k = k4 * 4 + e;
            int q = k >> 1;
            float vx = (e == 0) ? v0.x : (e == 1) ? v0.y : (e == 2) ? v0.z : v0.w;
            float vy = (e == 0) ? v1.x : (e == 1) ? v1.y : (e == 2) ? v1.z : v1.w;
            float vz = (e == 0) ? v2.x : (e == 1) ? v2.y : (e == 2) ? v2.z : v2.w;
            float kx = (k & 1) ? a[0][q].f.y : a[0][q].f.x;
            float ky = (k & 1) ? a[1][q].f.y : a[1][q].f.x;
            float kz = (k & 1) ? a[2][q].f.y : a[2][q].f.x;
            float r0, r1, r2;
            vact(vx, vy, vz, kx, ky, kz, r0, r1, r2);
            a0 += r0; a1 += r1; a2 += r2;
        }
    }
    int grp = pt >> 3, p = pt & 7;
    float* ob = g_bufA + grp * GSZ + p;
    ob[(0 * H + h) * P] = a0 * (1.0f / KNN);
    ob[(1 * H + h) * P] = a1 * (1.0f / KNN);
    ob[(2 * H + h) * P] = a2 * (1.0f / KNN);
}

// ---------------- per-point vec_lna: bufA -> bufB --------------------------
__global__ __launch_bounds__(128)
void lna_kernel(const float* __restrict__ W, const float* __restrict__ Wd) {
    int grp = blockIdx.x;
    int h = threadIdx.x, lane = h & 31, warp = h >> 5;
    __shared__ __align__(16) float ish[GSZ];
    __shared__ __align__(16) float vsh[GSZ];
    __shared__ unsigned long long redu[4][4];

    const float4* s4 = (const float4*)(g_bufA + grp * GSZ);
    float4* i4 = (float4*)ish;
#pragma unroll
    for (int t = 0; t < 6; ++t) i4[t * 128 + h] = s4[t * 128 + h];
    __syncthreads();

    F2 acc[3][4];
#pragma unroll
    for (int d = 0; d < 3; ++d)
#pragma unroll
        for (int q = 0; q < 4; ++q) acc[d][q].u = 0ull;
    matvec8(ish, W + h * H, acc);
    cnorm8(acc, redu, lane, warp);

#pragma unroll
    for (int d = 0; d < 3; ++d) {
        ulonglong2* vp = (ulonglong2*)(vsh + (d * H + h) * P);
        vp[0] = make_ulonglong2(acc[d][0].u, acc[d][1].u);
        vp[1] = make_ulonglong2(acc[d][2].u, acc[d][3].u);
    }
    __syncthreads();

    F2 kv[3][4];
#pragma unroll
    for (int d = 0; d < 3; ++d)
#pragma unroll
        for (int q = 0; q < 4; ++q) kv[d][q].u = 0ull;
    matvec8(vsh, Wd + h * H, kv);

    F2 r[3][4];
#pragma unroll
    for (int q = 0; q < 4; ++q) {
        float r0x, r1x, r2x, r0y, r1y, r2y;
        vact(acc[0][q].f.x, acc[1][q].f.x, acc[2][q].f.x,
             kv[0][q].f.x,  kv[1][q].f.x,  kv[2][q].f.x, r0x, r1x, r2x);
        vact(acc[0][q].f.y, acc[1][q].f.y, acc[2][q].f.y,
             kv[0][q].f.y,  kv[1][q].f.y,  kv[2][q].f.y, r0y, r1y, r2y);
        r[0][q].f = make_float2(r0x, r0y);
        r[1][q].f = make_float2(r1x, r1y);
        r[2][q].f = make_float2(r2x, r2y);
    }
    float* dst = g_bufB + grp * GSZ;
#pragma unroll
    for (int d = 0; d < 3; ++d) {
        ulonglong2* dp = (ulonglong2*)(dst + (d * H + h) * P);
        dp[0] = make_ulonglong2(r[d][0].u, r[d][1].u);
        dp[1] = make_ulonglong2(r[d][2].u, r[d][3].u);
    }
}

// ---------------- global mean over N of bufB -> g_g ------------------------
__global__ void mean_kernel() {
    int fl = blockIdx.x;                 // b*384 + c, c = d*128 + h
    int b = fl / (3 * H), c = fl % (3 * H);
    const float* base = g_bufB + (size_t)b * (NPT / P) * GSZ + c * P;
    float s = 0.0f;
    for (int i = threadIdx.x; i < 2 * (NPT / P); i += 128) {
        int g = i >> 1, q = i & 1;
        float4 v = *(const float4*)(base + g * GSZ + q * 4);
        s += (v.x + v.y) + (v.z + v.w);
    }
    __shared__ float rs[4];
    for (int o = 16; o > 0; o >>= 1) s += __shfl_xor_sync(0xffffffffu, s, o);
    if ((threadIdx.x & 31) == 0) rs[threadIdx.x >> 5] = s;
    __syncthreads();
    if (threadIdx.x == 0)
        g_g[fl] = (rs[0] + rs[1] + rs[2] + rs[3]) * (1.0f / NPT);
}

// ---------------- gpart = Gs[:, H:2H] @ g per batch ------------------------
__global__ void gpart_kernel(const float* __restrict__ Gi) {
    int b = blockIdx.x;
    int t = threadIdx.x;                 // 384 threads: t = d*128 + h
    __shared__ float gs[3 * H];
    gs[t] = g_g[b * 3 * H + t];
    __syncthreads();
    int d = t >> 7, h = t & 127;
    const float4* w4p = (const float4*)(Gi + h * (2 * H) + H);
    const float4* g4p = (const float4*)&gs[d * H];
    float s = 0.0f;
#pragma unroll
    for (int c = 0; c < H / 4; ++c) {
        float4 w = w4p[c], v = g4p[c];
        s += w.x * v.x + w.y * v.y + w.z * v.z + w.w * v.w;
    }
    g_gp[b * 3 * H + t] = s;
}

// -------- G-layer: vec_lna([h,g], Gs, Gds) + W_out accumulation ------------
__global__ __launch_bounds__(128)
void glayer_kernel(const float* __restrict__ Gl, const float* __restrict__ Gd,
                   const float* __restrict__ Wout, float* __restrict__ obig,
                   int layer) {
    int grp = blockIdx.x;
    int b = grp >> 8;
    int h = threadIdx.x, lane = h & 31, warp = h >> 5;
    __shared__ __align__(16) float ish[GSZ];
    __shared__ __align__(16) float vsh[GSZ];
    __shared__ unsigned long long redu[4][4];

    const float4* s4 = (const float4*)(g_bufB + grp * GSZ);
    float4* i4 = (float4*)ish;
#pragma unroll
    for (int t = 0; t < 6; ++t) i4[t * 128 + h] = s4[t * 128 + h];
    __syncthreads();

    F2 acc[3][4];
#pragma unroll
    for (int d = 0; d < 3; ++d) {
        float gv = g_gp[b * 3 * H + d * H + h];
        unsigned long long gp; PACKF2(gp, gv, gv);
#pragma unroll
        for (int q = 0; q < 4; ++q) acc[d][q].u = gp;
    }
    matvec8(ish, Gl + h * (2 * H), acc);
    cnorm8(acc, redu, lane, warp);

#pragma unroll
    for (int d = 0; d < 3; ++d) {
        ulonglong2* vp = (ulonglong2*)(vsh + (d * H + h) * P);
        vp[0] = make_ulonglong2(acc[d][0].u, acc[d][1].u);
        vp[1] = make_ulonglong2(acc[d][2].u, acc[d][3].u);
    }
    __syncthreads();

    F2 kv[3][4];
#pragma unroll
    for (int d = 0; d < 3; ++d)
#pragma unroll
        for (int q = 0; q < 4; ++q) kv[d][q].u = 0ull;
    matvec8(vsh, Gd + h * H, kv);

    F2 r[3][4];
#pragma unroll
    for (int q = 0; q < 4; ++q) {
        float r0x, r1x, r2x, r0y, r1y, r2y;
        vact(acc[0][q].f.x, acc[1][q].f.x, acc[2][q].f.x,
             kv[0][q].f.x,  kv[1][q].f.x,  kv[2][q].f.x, r0x, r1x, r2x);
        vact(acc[0][q].f.y, acc[1][q].f.y, acc[2][q].f.y,
             kv[0][q].f.y,  kv[1][q].f.y,  kv[2][q].f.y, r0y, r1y, r2y);
        r[0][q].f = make_float2(r0x, r0y);
        r[1][q].f = make_float2(r1x, r1y);
        r[2][q].f = make_float2(r2x, r2y);
    }
    float* dst = g_bufA + grp * GSZ;
#pragma unroll
    for (int d = 0; d < 3; ++d) {
        ulonglong2 lo = make_ulonglong2(r[d][0].u, r[d][1].u);
        ulonglong2 hi = make_ulonglong2(r[d][2].u, r[d][3].u);
        ulonglong2* dp = (ulonglong2*)(dst + (d * H + h) * P);
        dp[0] = lo; dp[1] = hi;
        ulonglong2* ip = (ulonglong2*)(ish + (d * H + h) * P);
        ip[0] = lo; ip[1] = hi;
    }
    __syncthreads();

    // W_out slice for this layer (thread h = output channel cd)
    F2 o[3][4];
#pragma unroll
    for (int d = 0; d < 3; ++d)
#pragma unroll
        for (int q = 0; q < 4; ++q) o[d][q].u = 0ull;
    matvec8(ish, Wout + h * (LL * H) + layer * H, o);

    int n0 = (grp & 255) * P;
#pragma unroll
    for (int d = 0; d < 3; ++d) {
        ulonglong2* dp = (ulonglong2*)(obig + ((b * CDIM + h) * 3 + d) * NPT + n0);
        if (layer == 0) {
            dp[0] = make_ulonglong2(o[d][0].u, o[d][1].u);
            dp[1] = make_ulonglong2(o[d][2].u, o[d][3].u);
        } else {
            ulonglong2 e0 = dp[0], e1 = dp[1];
            ADD2(o[d][0].u, e0.x); ADD2(o[d][1].u, e0.y);
            ADD2(o[d][2].u, e1.x); ADD2(o[d][3].u, e1.y);
            dp[0] = make_ulonglong2(o[d][0].u, o[d][1].u);
            dp[1] = make_ulonglong2(o[d][2].u, o[d][3].u);
        }
    }
}

// ---------------- final mean over N of the big output ----------------------
__global__ void outmean_kernel(const float* __restrict__ obig,
                               float* __restrict__ om) {
    int r = blockIdx.x;                  // (b*CD + cd)*3 + d
    float s = 0.0f;
    for (int n = threadIdx.x; n < NPT; n += blockDim.x)
        s += obig[r * NPT + n];
    __shared__ float rs[8];
    for (int o = 16; o > 0; o >>= 1) s += __shfl_xor_sync(0xffffffffu, s, o);
    if ((threadIdx.x & 31) == 0) rs[threadIdx.x >> 5] = s;
    __syncthreads();
    if (threadIdx.x == 0) {
        float t = 0.0f;
#pragma unroll
        for (int w = 0; w < 8; ++w) t += rs[w];
        om[r] = t * (1.0f / NPT);
    }
}

// ---------------------------------------------------------------------------
extern "C" void kernel_launch(void* const* d_in, const int* in_sizes, int n_in,
                              void* d_out, int out_size) {
    const float* x    = (const float*)d_in[0];
    const float* Win  = (const float*)d_in[1];
    const float* Wdin = (const float*)d_in[2];
    const float* Ws   = (const float*)d_in[3];
    const float* Wds  = (const float*)d_in[4];
    const float* Gs   = (const float*)d_in[5];
    const float* Gds  = (const float*)d_in[6];
    const float* Wout = (const float*)d_in[7];
    (void)in_sizes; (void)n_in; (void)out_size;

    float* out  = (float*)d_out;
    float* om   = out;                    // (B, CD, 3) mean
    float* obig = out + BB * CDIM * 3;    // (B, CD, 3, N)

    knn_kernel<<<dim3(NPT / 128, BB), 128>>>(x);
    input_kernel<<<BB * NPT, 128>>>(x, Win, Wdin);

    for (int i = 0; i < LL; ++i) {
        lna_kernel<<<NG, 128>>>(Ws + i * H * H, Wds + i * H * H);
        mean_kernel<<<BB * 3 * H, 128>>>();
        gpart_kernel<<<BB, 3 * H>>>(Gs + i * H * 2 * H);
        glayer_kernel<<<NG, 128>>>(Gs + i * H * 2 * H,
                                   Gds + i * H * H,
                                   Wout, obig, i);
    }
    outmean_kernel<<<BB * CDIM * 3, 256>>>(obig, om);
}